// round 5
// baseline (speedup 1.0000x reference)
#include <cuda_runtime.h>
#include <cuda_bf16.h>

// Problem constants
#define QN 256   // states
#define SN 128   // symbols
#define BN 1024  // batch
#define TN 128   // timesteps
#define MT 16    // batch elements per work item (MMA M = 16)
#define NSP 4    // n-split: CTAs per item, each owns 64 q' columns
#define NCH 64   // q' columns per CTA
#define GRIDX 192  // max items per step: sum ceil(c/16) <= 128 + 1024/16 = 192

// Device scratch (allocation-free rule: static __device__ globals)
__device__ unsigned g_Pbf[SN * QN * QN / 2];   // bf16x2 exp(A), [s][q][q'] : 16 MB
__device__ float g_alpha[2][BN * QN];          // ping-pong linear alphas (scaled)
__device__ int   g_order[TN * BN];
__device__ int4  g_items[TN * GRIDX];
__device__ int   g_nitems[TN];

// SMEM layout (bytes): A[16][256 bf16 + pad], P[256][64 bf16 + pad], sb[16]
#define A_OFF   0
#define A_ROW   528                      // 512 + 16 pad -> conflict-free ldmatrix
#define P_OFF   8448                     // 16 * 528
#define P_ROW   144                      // 128 + 16 pad
#define SB_OFF  (P_OFF + 256 * P_ROW)    // 8448 + 36864 = 45312
#define SH_BYTES (SB_OFF + 64)           // 45376 < 48KB static limit

// ---------------------------------------------------------------------------
__device__ __forceinline__ unsigned f22bf(float lo, float hi) {
    unsigned r;
    asm("cvt.rn.bf16x2.f32 %0, %1, %2;" : "=r"(r) : "f"(hi), "f"(lo));  // a->hi, b->lo
    return r;
}
__device__ __forceinline__ void ldmA(unsigned a[4], unsigned addr) {
    asm volatile("ldmatrix.sync.aligned.m8n8.x4.shared.b16 {%0,%1,%2,%3}, [%4];"
                 : "=r"(a[0]), "=r"(a[1]), "=r"(a[2]), "=r"(a[3]) : "r"(addr));
}
__device__ __forceinline__ void ldmBT2(unsigned b[2], unsigned addr) {
    asm volatile("ldmatrix.sync.aligned.m8n8.x2.trans.shared.b16 {%0,%1}, [%2];"
                 : "=r"(b[0]), "=r"(b[1]) : "r"(addr));
}
__device__ __forceinline__ void mma16816(float d[4], const unsigned a[4],
                                         unsigned b0, unsigned b1) {
    asm volatile("mma.sync.aligned.m16n8k16.row.col.f32.bf16.bf16.f32 "
                 "{%0,%1,%2,%3},{%4,%5,%6,%7},{%8,%9},{%0,%1,%2,%3};"
                 : "+f"(d[0]), "+f"(d[1]), "+f"(d[2]), "+f"(d[3])
                 : "r"(a[0]), "r"(a[1]), "r"(a[2]), "r"(a[3]), "r"(b0), "r"(b1));
}
__device__ __forceinline__ void cpasync16(unsigned saddr, const void* g) {
    asm volatile("cp.async.cg.shared.global [%0], [%1], 16;" :: "r"(saddr), "l"(g));
}
template <int N>
__device__ __forceinline__ void cp_wait() {
    asm volatile("cp.async.wait_group %0;" :: "n"(N));
}

// ---------------------------------------------------------------------------
// P_bf16[s][q][q'] = bf16(exp(A[q][s][q'])), packed as bf16x2 (q' pairs)
__global__ void exp_kernel(const float* __restrict__ A) {
    int i = blockIdx.x * 256 + threadIdx.x;   // one thread per q'-pair
    int j2 = i & 127;
    int q = (i >> 7) & 255;
    int s = i >> 15;
    float2 v = *(const float2*)(A + (q << 15) + (s << 8) + 2 * j2);
    g_Pbf[(s << 15) + (q << 7) + j2] = f22bf(__expf(v.x), __expf(v.y));
}

// ---------------------------------------------------------------------------
__global__ void init_kernel(const float* __restrict__ init) {
    int b = blockIdx.x;
    int q = threadIdx.x;
    float iv = init[q];
    g_alpha[0][b * QN + q] = (iv > 0.0f) ? iv : 0.0f;
}

// ---------------------------------------------------------------------------
// Per-timestep bucketing: items of <= MT elements sharing a symbol.
__global__ void bucket_kernel(const int* __restrict__ xs) {
    int t = blockIdx.x;
    int tid = threadIdx.x;
    __shared__ int cnt[SN];
    __shared__ int seg[SN];
    __shared__ int off[SN];
    if (tid < SN) cnt[tid] = 0;
    __syncthreads();
    for (int b = tid; b < BN; b += 256)
        atomicAdd(&cnt[xs[b * TN + t]], 1);
    __syncthreads();
    if (tid == 0) {
        int acc = 0;
        for (int s = 0; s < SN; s++) { seg[s] = acc; off[s] = acc; acc += cnt[s]; }
    }
    __syncthreads();
    for (int b = tid; b < BN; b += 256) {
        int s = xs[b * TN + t];
        int pos = atomicAdd(&off[s], 1);
        g_order[t * BN + pos] = b;
    }
    __syncthreads();
    if (tid == 0) {
        int ni = 0;
        for (int s = 0; s < SN; s++) {
            int c = cnt[s], st = seg[s];
            for (int o = 0; o < c; o += MT) {
                int m = c - o; if (m > MT) m = MT;
                g_items[t * GRIDX + ni] = make_int4(s, st + o, m, 0);
                ni++;
            }
        }
        g_nitems[t] = ni;
    }
}

// ---------------------------------------------------------------------------
// One FSA step via bf16 tensor-core GEMM per (item, n-chunk):
//   D[m=16 batch, n=64 q'] = alpha_bf16[m, k=256] x P_bf16[s][k, n-chunk]
// All 8 cp.async groups (32 KB P slice) issued up front; MMAs chase arrival.
// alpha staged with exact 2^-8 renorm; compensation added in final_kernel.
__global__ void __launch_bounds__(256) step_kernel(int t) {
    if (blockIdx.x >= g_nitems[t]) return;
    __shared__ __align__(16) unsigned char sh[SH_BYTES];
    unsigned shb = (unsigned)__cvta_generic_to_shared(sh);
    const int4 it = g_items[t * GRIDX + blockIdx.x];
    const int s = it.x, start = it.y, cnt = it.z;
    const int nc = blockIdx.y;                       // 0..NSP-1
    const float* __restrict__ pin = g_alpha[t & 1];
    float* __restrict__ pout = g_alpha[(t & 1) ^ 1];
    const int tid = threadIdx.x;
    const int w = tid >> 5, lane = tid & 31;

    // ---- fire all 8 P-slice fills (32 rows x 128B each; read-only data)
    const char* gP = (const char*)g_Pbf + ((size_t)s << 17) + (size_t)nc * 128;
    {
        int r_lo = tid >> 3;          // row within group
        int col = tid & 7;            // 16B chunk
        #pragma unroll
        for (int g = 0; g < 8; g++) {
            int r = (g << 5) + r_lo;
            cpasync16(shb + P_OFF + r * P_ROW + col * 16,
                      gP + (size_t)r * 512 + col * 16);
            asm volatile("cp.async.commit_group;");
        }
    }

    // ---- stage A: alpha * 2^-8 -> bf16 SMEM [16][256+pad]
    {
        int row = tid >> 4;     // batch slot 0..15
        int seg = tid & 15;     // 16 k-values each
        uint4 pk0, pk1;
        if (row < cnt) {
            int b = __ldg(&g_order[t * BN + start + row]);
            const float* p = pin + b * QN + seg * 16;
            float4 x0 = *(const float4*)p;
            float4 x1 = *(const float4*)(p + 4);
            float4 x2 = *(const float4*)(p + 8);
            float4 x3 = *(const float4*)(p + 12);
            const float sc = 0.00390625f;   // 2^-8 exact
            pk0.x = f22bf(x0.x * sc, x0.y * sc);
            pk0.y = f22bf(x0.z * sc, x0.w * sc);
            pk0.z = f22bf(x1.x * sc, x1.y * sc);
            pk0.w = f22bf(x1.z * sc, x1.w * sc);
            pk1.x = f22bf(x2.x * sc, x2.y * sc);
            pk1.y = f22bf(x2.z * sc, x2.w * sc);
            pk1.z = f22bf(x3.x * sc, x3.y * sc);
            pk1.w = f22bf(x3.z * sc, x3.w * sc);
        } else {
            pk0 = make_uint4(0, 0, 0, 0);
            pk1 = make_uint4(0, 0, 0, 0);
        }
        *(uint4*)(sh + A_OFF + row * A_ROW + seg * 32) = pk0;
        *(uint4*)(sh + A_OFF + row * A_ROW + seg * 32 + 16) = pk1;
        if (tid < MT)
            ((int*)(sh + SB_OFF))[tid] =
                (tid < cnt) ? __ldg(&g_order[t * BN + start + tid]) : 0;
    }

    float d[4] = {0.0f, 0.0f, 0.0f, 0.0f};
    const unsigned aA = shb + A_OFF + (lane & 15) * A_ROW + (lane >> 4) * 16;
    const unsigned aB = shb + P_OFF + (lane & 15) * P_ROW + w * 16;

    #define K16_STEP(k16)                                            \
    {                                                                \
        unsigned a[4], b[2];                                         \
        ldmA(a, aA + (k16) * 32);                                    \
        ldmBT2(b, aB + (k16) * 16 * P_ROW);                          \
        mma16816(d, a, b[0], b[1]);                                  \
    }

    // 4 waves: wait 2 more groups (64 k-rows), sync, consume 4 k16 tiles
    cp_wait<6>(); __syncthreads();
    K16_STEP(0)  K16_STEP(1)  K16_STEP(2)  K16_STEP(3)
    cp_wait<4>(); __syncthreads();
    K16_STEP(4)  K16_STEP(5)  K16_STEP(6)  K16_STEP(7)
    cp_wait<2>(); __syncthreads();
    K16_STEP(8)  K16_STEP(9)  K16_STEP(10) K16_STEP(11)
    cp_wait<0>(); __syncthreads();
    K16_STEP(12) K16_STEP(13) K16_STEP(14) K16_STEP(15)
    #undef K16_STEP

    // ---- epilogue: D frag (m = lane>>2 (+8), n = 2*(lane&3)+{0,1})
    const int* sb = (const int*)(sh + SB_OFF);
    int m0 = lane >> 2;
    int q0 = nc * NCH + w * 8 + 2 * (lane & 3);
    if (m0 < cnt)
        *(float2*)(pout + sb[m0] * QN + q0) = make_float2(d[0], d[1]);
    if (m0 + 8 < cnt)
        *(float2*)(pout + sb[m0 + 8] * QN + q0) = make_float2(d[2], d[3]);
}

// ---------------------------------------------------------------------------
// out[b] = log( sum_q alpha_lin[b][q] * exp(final[q]) ) + 128*ln(256)
__global__ void final_kernel(const float* __restrict__ finalw, float* __restrict__ out) {
    int b = blockIdx.x * 8 + (threadIdx.x >> 5);
    int lane = threadIdx.x & 31;
    const float* ar = g_alpha[0] + b * QN;   // T=128 even -> buffer 0
    float sum = 0.0f;
    #pragma unroll
    for (int i = 0; i < 8; i++) {
        int q = lane + 32 * i;
        sum += ar[q] * __expf(finalw[q]);
    }
    #pragma unroll
    for (int o = 16; o > 0; o >>= 1) sum += __shfl_xor_sync(0xFFFFFFFFu, sum, o);
    if (lane == 0)
        out[b] = logf(sum) + (float)(128.0 * 5.545177444479562);  // T * ln(256)
}

// ---------------------------------------------------------------------------
extern "C" void kernel_launch(void* const* d_in, const int* in_sizes, int n_in,
                              void* d_out, int out_size) {
    const float* A      = (const float*)d_in[0];  // [Q,S,Q] fp32
    const float* init   = (const float*)d_in[1];  // [Q]
    const float* finalw = (const float*)d_in[2];  // [Q]
    const int*   xs     = (const int*)d_in[3];    // [B,T] int32
    float* out = (float*)d_out;                   // [B]

    exp_kernel<<<(SN * QN * QN / 2) / 256, 256>>>(A);
    init_kernel<<<BN, QN>>>(init);
    bucket_kernel<<<TN, 256>>>(xs);
    for (int t = 0; t < TN; t++)
        step_kernel<<<dim3(GRIDX, NSP), 256>>>(t);
    final_kernel<<<BN / 8, 256>>>(finalw, out);
}

// round 6
// speedup vs baseline: 1.4726x; 1.4726x over previous
#include <cuda_runtime.h>
#include <cuda_bf16.h>

// Problem constants
#define QN 256   // states
#define SN 128   // symbols
#define BN 1024  // batch
#define TN 128   // timesteps
#define MT 16    // batch rows per MMA tile

// Device scratch (allocation-free rule: static __device__ globals)
__device__ unsigned g_Pbf[SN * QN * QN / 2];   // bf16x2 exp(A), [s][q][q'] : 16 MB
__device__ float    g_alpha[2][BN * QN];       // ping-pong linear alphas (scaled)
__device__ int      g_order[TN * BN];          // per-t batch indices grouped by symbol
__device__ int2     g_bkt[TN * SN];            // per (t,s): {start, cnt} in g_order
__device__ unsigned g_bar;                     // grid barrier counter (reset per run)

// Dynamic SMEM layout (bytes)
#define A_OFF   0
#define A_ROW   528                       // 256 bf16 + 16B pad (conflict-free ldmatrix)
#define P_OFF   8448                      // 16 * 528
#define P_ROW   528                       // 256 bf16 + 16B pad
#define SB_OFF  (P_OFF + 256 * P_ROW)     // 8448 + 135168 = 143616
#define SH_BYTES (SB_OFF + 64)            // 143680 (dynamic, opt-in)

// ---------------------------------------------------------------------------
__device__ __forceinline__ unsigned f22bf(float lo, float hi) {
    unsigned r;
    asm("cvt.rn.bf16x2.f32 %0, %1, %2;" : "=r"(r) : "f"(hi), "f"(lo));  // a->hi, b->lo
    return r;
}
__device__ __forceinline__ void ldmA(unsigned a[4], unsigned addr) {
    asm volatile("ldmatrix.sync.aligned.m8n8.x4.shared.b16 {%0,%1,%2,%3}, [%4];"
                 : "=r"(a[0]), "=r"(a[1]), "=r"(a[2]), "=r"(a[3]) : "r"(addr));
}
__device__ __forceinline__ void ldmBT(unsigned b[4], unsigned addr) {
    asm volatile("ldmatrix.sync.aligned.m8n8.x4.trans.shared.b16 {%0,%1,%2,%3}, [%4];"
                 : "=r"(b[0]), "=r"(b[1]), "=r"(b[2]), "=r"(b[3]) : "r"(addr));
}
__device__ __forceinline__ void mma16816(float d[4], const unsigned a[4],
                                         unsigned b0, unsigned b1) {
    asm volatile("mma.sync.aligned.m16n8k16.row.col.f32.bf16.bf16.f32 "
                 "{%0,%1,%2,%3},{%4,%5,%6,%7},{%8,%9},{%0,%1,%2,%3};"
                 : "+f"(d[0]), "+f"(d[1]), "+f"(d[2]), "+f"(d[3])
                 : "r"(a[0]), "r"(a[1]), "r"(a[2]), "r"(a[3]), "r"(b0), "r"(b1));
}
__device__ __forceinline__ void cpasync16(unsigned saddr, const void* g) {
    asm volatile("cp.async.cg.shared.global [%0], [%1], 16;" :: "r"(saddr), "l"(g));
}

// ---------------------------------------------------------------------------
// P_bf16[s][q][q'] = bf16(exp(A[q][s][q'])), packed as bf16x2 (q' pairs)
__global__ void exp_kernel(const float* __restrict__ A) {
    int i = blockIdx.x * 256 + threadIdx.x;   // one thread per q'-pair
    int j2 = i & 127;
    int q = (i >> 7) & 255;
    int s = i >> 15;
    float2 v = *(const float2*)(A + (q << 15) + (s << 8) + 2 * j2);
    g_Pbf[(s << 15) + (q << 7) + j2] = f22bf(__expf(v.x), __expf(v.y));
}

// ---------------------------------------------------------------------------
__global__ void init_kernel(const float* __restrict__ init) {
    int b = blockIdx.x;
    int q = threadIdx.x;
    float iv = init[q];
    g_alpha[0][b * QN + q] = (iv > 0.0f) ? iv : 0.0f;
}

// ---------------------------------------------------------------------------
// Per-timestep bucketing: group batch indices by symbol; emit {start,cnt} per
// (t,s). Also resets the grid barrier counter (stream-ordered before fsa_kernel,
// so every graph replay starts from g_bar == 0).
__global__ void bucket_kernel(const int* __restrict__ xs) {
    int t = blockIdx.x;
    int tid = threadIdx.x;
    if (t == 0 && tid == 0) g_bar = 0u;
    __shared__ int cnt[SN];
    __shared__ int seg[SN];
    __shared__ int off[SN];
    if (tid < SN) cnt[tid] = 0;
    __syncthreads();
    for (int b = tid; b < BN; b += 256)
        atomicAdd(&cnt[xs[b * TN + t]], 1);
    __syncthreads();
    if (tid == 0) {
        int acc = 0;
        for (int s = 0; s < SN; s++) { seg[s] = acc; off[s] = acc; acc += cnt[s]; }
    }
    __syncthreads();
    for (int b = tid; b < BN; b += 256) {
        int s = xs[b * TN + t];
        int pos = atomicAdd(&off[s], 1);
        g_order[t * BN + pos] = b;
    }
    __syncthreads();
    if (tid < SN)
        g_bkt[t * SN + tid] = make_int2(seg[tid], cnt[tid]);
}

// ---------------------------------------------------------------------------
// Persistent FSA kernel: one CTA per symbol, P[s] resident in SMEM for all
// 128 steps. Per step: GEMM the symbol's batch rows against resident P, then
// grid barrier (monotonic counter, release/acquire). Alpha reads use .cg
// (L2-only) because L1 is not coherent across the in-kernel barrier.
__global__ void __launch_bounds__(256, 1) fsa_kernel() {
    extern __shared__ __align__(16) unsigned char sh[];
    unsigned shb = (unsigned)__cvta_generic_to_shared(sh);
    const int s = blockIdx.x;
    const int tid = threadIdx.x, w = tid >> 5, lane = tid & 31;
    int* sb = (int*)(sh + SB_OFF);

    // ---- load P[s] (256 rows x 512B) into SMEM once
    {
        const char* gP = (const char*)g_Pbf + ((size_t)s << 17);
        for (int i = tid; i < 256 * 32; i += 256) {
            int r = i >> 5, c = i & 31;
            cpasync16(shb + P_OFF + r * P_ROW + c * 16, gP + (size_t)r * 512 + c * 16);
        }
        asm volatile("cp.async.commit_group;");
        asm volatile("cp.async.wait_group 0;");
        __syncthreads();
    }

    for (int t = 0; t < TN; t++) {
        const float* __restrict__ pin  = g_alpha[t & 1];
        float*       __restrict__ pout = g_alpha[(t & 1) ^ 1];
        const int2 bkt = g_bkt[t * SN + s];
        const int start = bkt.x, cnt = bkt.y;

        for (int o = 0; o < cnt; o += MT) {
            const int m = min(cnt - o, MT);

            // ---- stage A: alpha rows (* 2^-8 exact) -> bf16 SMEM [16][256+pad]
            {
                int row = tid >> 4;     // tile slot 0..15
                int seg = tid & 15;     // 16 k-values each
                uint4 pk0, pk1;
                if (row < m) {
                    int b = g_order[t * BN + start + o + row];
                    const float* p = pin + b * QN + seg * 16;
                    float4 x0 = __ldcg((const float4*)p);
                    float4 x1 = __ldcg((const float4*)(p + 4));
                    float4 x2 = __ldcg((const float4*)(p + 8));
                    float4 x3 = __ldcg((const float4*)(p + 12));
                    const float sc = 0.00390625f;   // 2^-8 exact
                    pk0.x = f22bf(x0.x * sc, x0.y * sc);
                    pk0.y = f22bf(x0.z * sc, x0.w * sc);
                    pk0.z = f22bf(x1.x * sc, x1.y * sc);
                    pk0.w = f22bf(x1.z * sc, x1.w * sc);
                    pk1.x = f22bf(x2.x * sc, x2.y * sc);
                    pk1.y = f22bf(x2.z * sc, x2.w * sc);
                    pk1.z = f22bf(x3.x * sc, x3.y * sc);
                    pk1.w = f22bf(x3.z * sc, x3.w * sc);
                } else {
                    pk0 = make_uint4(0, 0, 0, 0);
                    pk1 = make_uint4(0, 0, 0, 0);
                }
                *(uint4*)(sh + A_OFF + row * A_ROW + seg * 32) = pk0;
                *(uint4*)(sh + A_OFF + row * A_ROW + seg * 32 + 16) = pk1;
                if (tid < MT)
                    sb[tid] = (tid < m) ? g_order[t * BN + start + o + tid] : 0;
            }
            __syncthreads();

            // ---- GEMM: D[16, n=32 cols per warp] += A[16,256] x P[256, n]
            float d[4][4];
            #pragma unroll
            for (int j = 0; j < 4; j++)
                #pragma unroll
                for (int r = 0; r < 4; r++) d[j][r] = 0.0f;

            const unsigned aA = shb + A_OFF + (lane & 15) * A_ROW + (lane >> 4) * 16;
            const unsigned aB = shb + P_OFF + (lane & 15) * P_ROW
                                + (w * 32 + (lane >> 4) * 8) * 2;
            #pragma unroll
            for (int k16 = 0; k16 < 16; k16++) {
                unsigned a[4], b[8];
                ldmA(a, aA + k16 * 32);
                unsigned baddr = aB + k16 * 16 * P_ROW;
                ldmBT(b + 0, baddr);        // n-tiles 0,1
                ldmBT(b + 4, baddr + 32);   // n-tiles 2,3
                mma16816(d[0], a, b[0], b[1]);
                mma16816(d[1], a, b[2], b[3]);
                mma16816(d[2], a, b[4], b[5]);
                mma16816(d[3], a, b[6], b[7]);
            }

            // ---- epilogue: D frag (m = lane>>2 (+8), n = w*32 + 2*(lane&3) + j*8)
            int m0 = lane >> 2;
            int q0 = w * 32 + 2 * (lane & 3);
            #pragma unroll
            for (int j = 0; j < 4; j++) {
                int n = q0 + j * 8;
                if (m0 < m)
                    *(float2*)(pout + sb[m0] * QN + n) = make_float2(d[j][0], d[j][1]);
                if (m0 + 8 < m)
                    *(float2*)(pout + sb[m0 + 8] * QN + n) = make_float2(d[j][2], d[j][3]);
            }
            __syncthreads();   // protect A/sb before next tile restage
        }

        // ---- grid barrier: all 128 CTAs arrive, monotonic target
        __threadfence();       // each thread's global writes -> device scope
        __syncthreads();
        if (tid == 0) {
            atomicAdd(&g_bar, 1u);
            const unsigned target = (unsigned)(t + 1) * (unsigned)SN;
            unsigned v;
            do {
                asm volatile("ld.acquire.gpu.u32 %0, [%1];" : "=r"(v) : "l"(&g_bar));
            } while (v < target);
        }
        __syncthreads();
    }
}

// ---------------------------------------------------------------------------
// out[b] = log( sum_q alpha_lin[b][q] * exp(final[q]) ) + 128*ln(256)
__global__ void final_kernel(const float* __restrict__ finalw, float* __restrict__ out) {
    int b = blockIdx.x * 8 + (threadIdx.x >> 5);
    int lane = threadIdx.x & 31;
    const float* ar = g_alpha[0] + b * QN;   // T=128 even -> buffer 0
    float sum = 0.0f;
    #pragma unroll
    for (int i = 0; i < 8; i++) {
        int q = lane + 32 * i;
        sum += ar[q] * __expf(finalw[q]);
    }
    #pragma unroll
    for (int o = 16; o > 0; o >>= 1) sum += __shfl_xor_sync(0xFFFFFFFFu, sum, o);
    if (lane == 0)
        out[b] = logf(sum) + (float)(128.0 * 5.545177444479562);  // T * ln(256)
}

// ---------------------------------------------------------------------------
extern "C" void kernel_launch(void* const* d_in, const int* in_sizes, int n_in,
                              void* d_out, int out_size) {
    const float* A      = (const float*)d_in[0];  // [Q,S,Q] fp32
    const float* init   = (const float*)d_in[1];  // [Q]
    const float* finalw = (const float*)d_in[2];  // [Q]
    const int*   xs     = (const int*)d_in[3];    // [B,T] int32
    float* out = (float*)d_out;                   // [B]

    cudaFuncSetAttribute(fsa_kernel,
                         cudaFuncAttributeMaxDynamicSharedMemorySize, SH_BYTES);

    exp_kernel<<<(SN * QN * QN / 2) / 256, 256>>>(A);
    init_kernel<<<BN, QN>>>(init);
    bucket_kernel<<<TN, 256>>>(xs);
    fsa_kernel<<<SN, 256, SH_BYTES>>>();
    final_kernel<<<BN / 8, 256>>>(finalw, out);
}

// round 7
// speedup vs baseline: 1.5139x; 1.0280x over previous
#include <cuda_runtime.h>
#include <cuda_bf16.h>

// Problem constants
#define QN 256   // states
#define SN 128   // symbols
#define BN 1024  // batch
#define TN 128   // timesteps
#define MT 16    // batch rows per MMA tile
#define NTHREADS 512

// Device scratch (allocation-free rule: static __device__ globals)
__device__ unsigned g_Pbf[SN * QN * QN / 2];   // bf16x2 exp(A), [s][q][q'] : 16 MB
__device__ float    g_alpha[2][BN * QN];       // ping-pong linear alphas (scaled)
__device__ int      g_order[TN * BN];          // per-t batch indices grouped by symbol
__device__ int2     g_bkt[TN * SN];            // per (t,s): {start, cnt} in g_order
__device__ unsigned g_bar;                     // grid barrier counter (reset per run)

// Dynamic SMEM layout (bytes)
#define A_OFF   0
#define A_ROW   528                       // 256 bf16 + 16B pad (conflict-free ldmatrix)
#define P_OFF   (32 * A_ROW)              // A holds up to 32 rows: 16896
#define P_ROW   528
#define SB_OFF  (P_OFF + 256 * P_ROW)     // 16896 + 135168 = 152064
#define SH_BYTES (SB_OFF + 128)           // 152192 (dynamic, opt-in; 1 CTA/SM)

// ---------------------------------------------------------------------------
__device__ __forceinline__ unsigned f22bf(float lo, float hi) {
    unsigned r;
    asm("cvt.rn.bf16x2.f32 %0, %1, %2;" : "=r"(r) : "f"(hi), "f"(lo));  // a->hi, b->lo
    return r;
}
__device__ __forceinline__ void ldmA(unsigned a[4], unsigned addr) {
    asm volatile("ldmatrix.sync.aligned.m8n8.x4.shared.b16 {%0,%1,%2,%3}, [%4];"
                 : "=r"(a[0]), "=r"(a[1]), "=r"(a[2]), "=r"(a[3]) : "r"(addr));
}
__device__ __forceinline__ void ldmBT(unsigned b[4], unsigned addr) {
    asm volatile("ldmatrix.sync.aligned.m8n8.x4.trans.shared.b16 {%0,%1,%2,%3}, [%4];"
                 : "=r"(b[0]), "=r"(b[1]), "=r"(b[2]), "=r"(b[3]) : "r"(addr));
}
__device__ __forceinline__ void mma16816(float d[4], const unsigned a[4],
                                         unsigned b0, unsigned b1) {
    asm volatile("mma.sync.aligned.m16n8k16.row.col.f32.bf16.bf16.f32 "
                 "{%0,%1,%2,%3},{%4,%5,%6,%7},{%8,%9},{%0,%1,%2,%3};"
                 : "+f"(d[0]), "+f"(d[1]), "+f"(d[2]), "+f"(d[3])
                 : "r"(a[0]), "r"(a[1]), "r"(a[2]), "r"(a[3]), "r"(b0), "r"(b1));
}
__device__ __forceinline__ void cpasync16(unsigned saddr, const void* g) {
    asm volatile("cp.async.cg.shared.global [%0], [%1], 16;" :: "r"(saddr), "l"(g));
}

// ---------------------------------------------------------------------------
// P_bf16[s][q][q'] = bf16(exp(A[q][s][q'])), packed as bf16x2 (q' pairs)
__global__ void exp_kernel(const float* __restrict__ A) {
    int i = blockIdx.x * 256 + threadIdx.x;   // one thread per q'-pair
    int j2 = i & 127;
    int q = (i >> 7) & 255;
    int s = i >> 15;
    float2 v = *(const float2*)(A + (q << 15) + (s << 8) + 2 * j2);
    g_Pbf[(s << 15) + (q << 7) + j2] = f22bf(__expf(v.x), __expf(v.y));
}

// ---------------------------------------------------------------------------
__global__ void init_kernel(const float* __restrict__ init) {
    int b = blockIdx.x;
    int q = threadIdx.x;
    float iv = init[q];
    g_alpha[0][b * QN + q] = (iv > 0.0f) ? iv : 0.0f;
}

// ---------------------------------------------------------------------------
// Per-timestep bucketing; also resets the grid barrier counter (stream-ordered
// before fsa_kernel, so every graph replay starts from g_bar == 0).
__global__ void bucket_kernel(const int* __restrict__ xs) {
    int t = blockIdx.x;
    int tid = threadIdx.x;
    if (t == 0 && tid == 0) g_bar = 0u;
    __shared__ int cnt[SN];
    __shared__ int seg[SN];
    __shared__ int off[SN];
    if (tid < SN) cnt[tid] = 0;
    __syncthreads();
    for (int b = tid; b < BN; b += 256)
        atomicAdd(&cnt[xs[b * TN + t]], 1);
    __syncthreads();
    if (tid == 0) {
        int acc = 0;
        for (int s = 0; s < SN; s++) { seg[s] = acc; off[s] = acc; acc += cnt[s]; }
    }
    __syncthreads();
    for (int b = tid; b < BN; b += 256) {
        int s = xs[b * TN + t];
        int pos = atomicAdd(&off[s], 1);
        g_order[t * BN + pos] = b;
    }
    __syncthreads();
    if (tid < SN)
        g_bkt[t * SN + tid] = make_int2(seg[tid], cnt[tid]);
}

// ---------------------------------------------------------------------------
// Persistent FSA kernel: one CTA per symbol, P[s] SMEM-resident for all steps.
// 16 warps. cnt<=16: all warps share one M=16 tile (16 cols each).
// cnt>16: warp groups 0-7 / 8-15 process two tiles concurrently (32 cols each).
// Grid barrier: release-add + acquire-poll on a monotonic counter.
__global__ void __launch_bounds__(NTHREADS, 1) fsa_kernel() {
    extern __shared__ __align__(16) unsigned char sh[];
    unsigned shb = (unsigned)__cvta_generic_to_shared(sh);
    const int s = blockIdx.x;
    const int tid = threadIdx.x, w = tid >> 5, lane = tid & 31;
    int* sb = (int*)(sh + SB_OFF);

    // ---- load P[s] (256 rows x 512B) into SMEM once
    {
        const char* gP = (const char*)g_Pbf + ((size_t)s << 17);
        for (int i = tid; i < 256 * 32; i += NTHREADS) {
            int r = i >> 5, c = i & 31;
            cpasync16(shb + P_OFF + r * P_ROW + c * 16, gP + (size_t)r * 512 + c * 16);
        }
        asm volatile("cp.async.commit_group;");
        asm volatile("cp.async.wait_group 0;");
        __syncthreads();
    }

    const float sc = 0.00390625f;   // 2^-8 exact per-step renorm

    for (int t = 0; t < TN; t++) {
        const float* __restrict__ pin  = g_alpha[t & 1];
        float*       __restrict__ pout = g_alpha[(t & 1) ^ 1];
        const int2 bkt = g_bkt[t * SN + s];
        const int start = bkt.x, cnt = bkt.y;

        int o = 0;
        while (o < cnt) {
            const int rem = cnt - o;
            if (rem > MT) {
                // ================= two-tile mode (32 rows, warp-split) =====
                const int m = min(rem, 32);
                {   // stage 32 rows: row = tid>>4, 16 floats/thread
                    int row = tid >> 4, seg = tid & 15;
                    uint4 pk0 = make_uint4(0,0,0,0), pk1 = make_uint4(0,0,0,0);
                    if (row < m) {
                        int b = g_order[t * BN + start + o + row];
                        const float* p = pin + b * QN + seg * 16;
                        float4 x0 = __ldcg((const float4*)p);
                        float4 x1 = __ldcg((const float4*)(p + 4));
                        float4 x2 = __ldcg((const float4*)(p + 8));
                        float4 x3 = __ldcg((const float4*)(p + 12));
                        pk0.x = f22bf(x0.x*sc, x0.y*sc); pk0.y = f22bf(x0.z*sc, x0.w*sc);
                        pk0.z = f22bf(x1.x*sc, x1.y*sc); pk0.w = f22bf(x1.z*sc, x1.w*sc);
                        pk1.x = f22bf(x2.x*sc, x2.y*sc); pk1.y = f22bf(x2.z*sc, x2.w*sc);
                        pk1.z = f22bf(x3.x*sc, x3.y*sc); pk1.w = f22bf(x3.z*sc, x3.w*sc);
                    }
                    *(uint4*)(sh + A_OFF + row * A_ROW + seg * 32) = pk0;
                    *(uint4*)(sh + A_OFF + row * A_ROW + seg * 32 + 16) = pk1;
                    if (tid < 32)
                        sb[tid] = (tid < m) ? g_order[t * BN + start + o + tid] : 0;
                }
                __syncthreads();

                const int g = w >> 3, wg = w & 7;        // tile group, warp-in-group
                const int mg = min(m - g * MT, MT);      // rows in this tile (tile0=16)
                float d[4][4];
                #pragma unroll
                for (int j = 0; j < 4; j++)
                    #pragma unroll
                    for (int r = 0; r < 4; r++) d[j][r] = 0.0f;

                const unsigned aA = shb + A_OFF + (g * MT + (lane & 15)) * A_ROW
                                    + (lane >> 4) * 16;
                const unsigned aB = shb + P_OFF + (lane & 15) * P_ROW
                                    + (wg * 32 + (lane >> 4) * 8) * 2;
                #pragma unroll
                for (int k16 = 0; k16 < 16; k16++) {
                    unsigned a[4], b[8];
                    ldmA(a, aA + k16 * 32);
                    unsigned baddr = aB + k16 * 16 * P_ROW;
                    ldmBT(b + 0, baddr);
                    ldmBT(b + 4, baddr + 32);
                    mma16816(d[0], a, b[0], b[1]);
                    mma16816(d[1], a, b[2], b[3]);
                    mma16816(d[2], a, b[4], b[5]);
                    mma16816(d[3], a, b[6], b[7]);
                }
                int m0 = lane >> 2;
                int q0 = wg * 32 + 2 * (lane & 3);
                #pragma unroll
                for (int j = 0; j < 4; j++) {
                    int n = q0 + j * 8;
                    if (m0 < mg)
                        *(float2*)(pout + sb[g*MT + m0] * QN + n)
                            = make_float2(d[j][0], d[j][1]);
                    if (m0 + 8 < mg)
                        *(float2*)(pout + sb[g*MT + m0 + 8] * QN + n)
                            = make_float2(d[j][2], d[j][3]);
                }
                __syncthreads();
                o += 32;
            } else {
                // ================= single-tile mode (<=16 rows, 16 warps) ==
                const int m = rem;
                {   // stage 16 rows: row = tid>>5, 8 floats/thread
                    int row = tid >> 5, seg = tid & 31;
                    uint4 pk = make_uint4(0,0,0,0);
                    if (row < m) {
                        int b = g_order[t * BN + start + o + row];
                        const float* p = pin + b * QN + seg * 8;
                        float4 x0 = __ldcg((const float4*)p);
                        float4 x1 = __ldcg((const float4*)(p + 4));
                        pk.x = f22bf(x0.x*sc, x0.y*sc); pk.y = f22bf(x0.z*sc, x0.w*sc);
                        pk.z = f22bf(x1.x*sc, x1.y*sc); pk.w = f22bf(x1.z*sc, x1.w*sc);
                    }
                    *(uint4*)(sh + A_OFF + row * A_ROW + seg * 16) = pk;
                    if (tid < MT)
                        sb[tid] = (tid < m) ? g_order[t * BN + start + o + tid] : 0;
                }
                __syncthreads();

                float d[2][4];
                #pragma unroll
                for (int j = 0; j < 2; j++)
                    #pragma unroll
                    for (int r = 0; r < 4; r++) d[j][r] = 0.0f;

                const unsigned aA = shb + A_OFF + (lane & 15) * A_ROW
                                    + (lane >> 4) * 16;
                const unsigned aB = shb + P_OFF + (lane & 15) * P_ROW
                                    + (w * 16 + (lane >> 4) * 8) * 2;
                #pragma unroll
                for (int k16 = 0; k16 < 16; k16++) {
                    unsigned a[4], b[4];
                    ldmA(a, aA + k16 * 32);
                    ldmBT(b, aB + k16 * 16 * P_ROW);   // n-tiles w*16, w*16+8
                    mma16816(d[0], a, b[0], b[1]);
                    mma16816(d[1], a, b[2], b[3]);
                }
                int m0 = lane >> 2;
                int q0 = w * 16 + 2 * (lane & 3);
                #pragma unroll
                for (int j = 0; j < 2; j++) {
                    int n = q0 + j * 8;
                    if (m0 < m)
                        *(float2*)(pout + sb[m0] * QN + n)
                            = make_float2(d[j][0], d[j][1]);
                    if (m0 + 8 < m)
                        *(float2*)(pout + sb[m0 + 8] * QN + n)
                            = make_float2(d[j][2], d[j][3]);
                }
                __syncthreads();
                o += MT;
            }
        }

        // ---- grid barrier: release-add, acquire-poll, monotonic target
        if (tid == 0) {
            asm volatile("red.release.gpu.global.add.u32 [%0], 1;"
                         :: "l"(&g_bar) : "memory");
            const unsigned target = (unsigned)(t + 1) * (unsigned)SN;
            unsigned v;
            do {
                asm volatile("ld.acquire.gpu.u32 %0, [%1];" : "=r"(v) : "l"(&g_bar));
            } while (v < target);
        }
        __syncthreads();
    }
}

// ---------------------------------------------------------------------------
// out[b] = log( sum_q alpha_lin[b][q] * exp(final[q]) ) + 128*ln(256)
__global__ void final_kernel(const float* __restrict__ finalw, float* __restrict__ out) {
    int b = blockIdx.x * 8 + (threadIdx.x >> 5);
    int lane = threadIdx.x & 31;
    const float* ar = g_alpha[0] + b * QN;   // T=128 even -> buffer 0
    float sum = 0.0f;
    #pragma unroll
    for (int i = 0; i < 8; i++) {
        int q = lane + 32 * i;
        sum += ar[q] * __expf(finalw[q]);
    }
    #pragma unroll
    for (int o = 16; o > 0; o >>= 1) sum += __shfl_xor_sync(0xFFFFFFFFu, sum, o);
    if (lane == 0)
        out[b] = logf(sum) + (float)(128.0 * 5.545177444479562);  // T * ln(256)
}

// ---------------------------------------------------------------------------
extern "C" void kernel_launch(void* const* d_in, const int* in_sizes, int n_in,
                              void* d_out, int out_size) {
    const float* A      = (const float*)d_in[0];  // [Q,S,Q] fp32
    const float* init   = (const float*)d_in[1];  // [Q]
    const float* finalw = (const float*)d_in[2];  // [Q]
    const int*   xs     = (const int*)d_in[3];    // [B,T] int32
    float* out = (float*)d_out;                   // [B]

    cudaFuncSetAttribute(fsa_kernel,
                         cudaFuncAttributeMaxDynamicSharedMemorySize, SH_BYTES);

    exp_kernel<<<(SN * QN * QN / 2) / 256, 256>>>(A);
    init_kernel<<<BN, QN>>>(init);
    bucket_kernel<<<TN, 256>>>(xs);
    fsa_kernel<<<SN, NTHREADS, SH_BYTES>>>();
    final_kernel<<<BN / 8, 256>>>(finalw, out);
}